// round 17
// baseline (speedup 1.0000x reference)
#include <cuda_runtime.h>
#include <cuda_fp16.h>
#include <cstdint>
#include <math.h>

#define BATCH 2
#define SEQ   2048
#define DIM   4096
#define KV_DIM 1024
#define NHQ   32
#define NHK   8
#define HD    128
#define MROWS (BATCH*SEQ)

// scratch (no allocations allowed)
__device__ __half g_hx[MROWS*DIM];
__device__ __half g_hwq[DIM*DIM];
__device__ __half g_hwk[KV_DIM*DIM];
__device__ __half g_hwv[KV_DIM*DIM];
__device__ __half g_hwo[DIM*DIM];
__device__ __half g_hq[MROWS*DIM];
__device__ __half g_hk[MROWS*KV_DIM];
__device__ __half g_hv[MROWS*KV_DIM];
__device__ __half g_ho[MROWS*DIM];
__device__ float g_invf[64];

// ==================================================================
// helpers
// ==================================================================
__device__ __forceinline__ void ldsm4(uint32_t& r0, uint32_t& r1,
                                      uint32_t& r2, uint32_t& r3, uint32_t addr)
{
    asm volatile("ldmatrix.sync.aligned.m8n8.x4.shared.b16 {%0,%1,%2,%3}, [%4];"
                 : "=r"(r0), "=r"(r1), "=r"(r2), "=r"(r3) : "r"(addr));
}

__device__ __forceinline__ void ldsm4t(uint32_t& r0, uint32_t& r1,
                                       uint32_t& r2, uint32_t& r3, uint32_t addr)
{
    asm volatile("ldmatrix.sync.aligned.m8n8.x4.trans.shared.b16 {%0,%1,%2,%3}, [%4];"
                 : "=r"(r0), "=r"(r1), "=r"(r2), "=r"(r3) : "r"(addr));
}

__device__ __forceinline__ void mma_f16(float* d, const uint32_t* a,
                                        uint32_t b0, uint32_t b1)
{
    asm volatile("mma.sync.aligned.m16n8k16.row.col.f32.f16.f16.f32 "
                 "{%0,%1,%2,%3},{%4,%5,%6,%7},{%8,%9},{%0,%1,%2,%3};"
                 : "+f"(d[0]), "+f"(d[1]), "+f"(d[2]), "+f"(d[3])
                 : "r"(a[0]), "r"(a[1]), "r"(a[2]), "r"(a[3]),
                   "r"(b0), "r"(b1));
}

__device__ __forceinline__ void cp_async16(uint32_t dst, const void* src)
{
    asm volatile("cp.async.cg.shared.global [%0], [%1], 16;" :: "r"(dst), "l"(src));
}
__device__ __forceinline__ void cp_commit()
{
    asm volatile("cp.async.commit_group;");
}
template<int N> __device__ __forceinline__ void cp_wait()
{
    asm volatile("cp.async.wait_group %0;" :: "n"(N));
}

// ==================================================================
// conversion kernel (all 5 inputs in one launch)
// ==================================================================
__global__ void to_half5_kernel(const float* s0, __half* d0, int n0,
                                const float* s1, __half* d1, int n1,
                                const float* s2, __half* d2, int n2,
                                const float* s3, __half* d3, int n3,
                                const float* s4, __half* d4, int n4)
{
    int j = blockIdx.x * blockDim.x + threadIdx.x;
    const float* in;
    __half* out;
    if (j < n0) { in = s0; out = d0; }
    else {
        j -= n0;
        if (j < n1) { in = s1; out = d1; }
        else {
            j -= n1;
            if (j < n2) { in = s2; out = d2; }
            else {
                j -= n2;
                if (j < n3) { in = s3; out = d3; }
                else {
                    j -= n3;
                    if (j >= n4) { return; }
                    in = s4; out = d4;
                }
            }
        }
    }
    float4 v = ((const float4*)in)[j];
    ((__half2*)out)[j * 2]     = __floats2half2_rn(v.x, v.y);
    ((__half2*)out)[j * 2 + 1] = __floats2half2_rn(v.z, v.w);
}

// inv_freq table (bit-identical to original per-thread calc)
__global__ void invf_kernel(float* __restrict__ tbl)
{
    int i = threadIdx.x;
    if (i < 64) {
        tbl[i] = (float)pow(10000.0, -(double)i / 64.0);
    }
}

// ==================================================================
// FP16 GEMM body — proven core + fragment pipeline.
// mode 0: fp32 store; mode 1: fp16 store; mode 2: rope+fp16 store
// (rope math identical to the old rope kernel, applied to the same
//  fp32 accumulators -> bit-identical results)
// ==================================================================
#define HBM 128
#define HBN 128
#define HBK 64
#define HSTAGES 3
#define HSTAGE_BYTES 32768
#define HGEMM_SMEM (HSTAGES*HSTAGE_BYTES)

__device__ __forceinline__ void gemm_body(const __half* __restrict__ A,
                                          const __half* __restrict__ B,
                                          float* __restrict__ Cf32,
                                          __half* __restrict__ Ch16,
                                          int N, int K, int bm, int bn,
                                          char* hsm, int mode,
                                          const float* __restrict__ invf_tbl,
                                          const int* __restrict__ sp,
                                          float rscale)
{
    const uint32_t su = (uint32_t)__cvta_generic_to_shared(hsm);

    const int tid  = threadIdx.x;
    const int lane = tid & 31;
    const int warp = tid >> 5;
    const int wm   = warp & 3;
    const int wn   = warp >> 2;

    const int lrow = tid >> 1;
    const int lu0  = (tid & 1) * 4;
    const __half* Ap = A + (long)(bm * HBM + lrow) * K;
    const __half* Bp = B + (long)(bn * HBN + lrow) * K;
    const uint32_t aDst = su + (uint32_t)(lrow * 128);
    const uint32_t bDst = aDst + 16384u;
    const int lsw = lrow & 7;

    const int grp = lane >> 3;
    const int lr  = lane & 7;
    const int frow = lr + 8 * (grp & 1);
    const int gk   = grp >> 1;
    const int rowA = wm * 32 + frow;
    const int rowB = wn * 64 + frow;
    const int swA = rowA & 7;
    const int swB = rowB & 7;
    const uint32_t aRowOff = (uint32_t)rowA * 128u;
    const uint32_t bRowOff = (uint32_t)rowB * 128u;

    float c[2][8][4];
    for (int mt = 0; mt < 2; mt++) {
        for (int nt = 0; nt < 8; nt++) {
            for (int r = 0; r < 4; r++) {
                c[mt][nt][r] = 0.f;
            }
        }
    }

    const int T = K / HBK;

    for (int s = 0; s < HSTAGES - 1; s++) {
        int k0 = s * HBK;
        uint32_t ad = aDst + (uint32_t)s * HSTAGE_BYTES;
        uint32_t bd = bDst + (uint32_t)s * HSTAGE_BYTES;
#pragma unroll
        for (int p = 0; p < 4; p++) {
            int u = lu0 + p;
            uint32_t so = (uint32_t)((u ^ lsw) << 4);
            cp_async16(ad + so, Ap + k0 + u * 8);
            cp_async16(bd + so, Bp + k0 + u * 8);
        }
        cp_commit();
    }

    uint32_t af0[2][4];
    uint32_t af1[2][4];
    uint32_t bf[2][4][4];

    auto load_frags = [&](uint32_t Abase, uint32_t Bbase, int kk, int buf) {
        int u = kk * 2 + gk;
        uint32_t aAddr = Abase + aRowOff + (uint32_t)(((u ^ swA) & 7) << 4) +
                         (uint32_t)((u & 8) << 4);
        ldsm4(af0[buf][0], af0[buf][1], af0[buf][2], af0[buf][3], aAddr);
        ldsm4(af1[buf][0], af1[buf][1], af1[buf][2], af1[buf][3], aAddr + 2048u);
#pragma unroll
        for (int jp = 0; jp < 4; jp++) {
            uint32_t bAddr = Bbase + bRowOff + (uint32_t)(jp * 2048) +
                             (uint32_t)(((u ^ swB) & 7) << 4) +
                             (uint32_t)((u & 8) << 4);
            ldsm4(bf[buf][jp][0], bf[buf][jp][1], bf[buf][jp][2], bf[buf][jp][3], bAddr);
        }
    };

    for (int ks = 0; ks < T; ks++) {
        cp_wait<HSTAGES - 2>();
        __syncthreads();

        int nk = ks + HSTAGES - 1;
        if (nk < T) {
            int slot = nk % HSTAGES;
            int k0 = nk * HBK;
            uint32_t ad = aDst + (uint32_t)slot * HSTAGE_BYTES;
            uint32_t bd = bDst + (uint32_t)slot * HSTAGE_BYTES;
#pragma unroll
            for (int p = 0; p < 4; p++) {
                int u = lu0 + p;
                uint32_t so = (uint32_t)((u ^ lsw) << 4);
                cp_async16(ad + so, Ap + k0 + u * 8);
                cp_async16(bd + so, Bp + k0 + u * 8);
            }
            cp_commit();
        }

        const uint32_t Abase = su + (uint32_t)((ks % HSTAGES) * HSTAGE_BYTES);
        const uint32_t Bbase = Abase + 16384u;

        load_frags(Abase, Bbase, 0, 0);
#pragma unroll
        for (int kk = 0; kk < 4; kk++) {
            int cur = kk & 1;
            if (kk < 3) {
                load_frags(Abase, Bbase, kk + 1, cur ^ 1);
            }
#pragma unroll
            for (int nt = 0; nt < 8; nt++) {
                uint32_t b0 = bf[cur][nt >> 1][nt & 1];
                uint32_t b1 = bf[cur][nt >> 1][(nt & 1) + 2];
                mma_f16(c[0][nt], af0[cur], b0, b1);
                mma_f16(c[1][nt], af1[cur], b0, b1);
            }
        }
    }

    const int g  = lane >> 2;
    const int t2 = (lane & 3) * 2;
    if (mode == 0) {
        for (int mt = 0; mt < 2; mt++) {
            int row0 = bm * HBM + wm * 32 + mt * 16 + g;
            for (int nt = 0; nt < 8; nt++) {
                int col = bn * HBN + wn * 64 + nt * 8 + t2;
                *(float2*)(Cf32 + (long)row0 * N + col)       = make_float2(c[mt][nt][0], c[mt][nt][1]);
                *(float2*)(Cf32 + (long)(row0 + 8) * N + col) = make_float2(c[mt][nt][2], c[mt][nt][3]);
            }
        }
    } else if (mode == 1) {
        for (int mt = 0; mt < 2; mt++) {
            int row0 = bm * HBM + wm * 32 + mt * 16 + g;
            for (int nt = 0; nt < 8; nt++) {
                int col = bn * HBN + wn * 64 + nt * 8 + t2;
                *(__half2*)(Ch16 + (long)row0 * N + col) =
                    __floats2half2_rn(c[mt][nt][0], c[mt][nt][1]);
                *(__half2*)(Ch16 + (long)(row0 + 8) * N + col) =
                    __floats2half2_rn(c[mt][nt][2], c[mt][nt][3]);
            }
        }
    } else {
        // rope + fp16 store; math identical to the old rope kernel
        const int sp0 = sp[0];
        for (int mt = 0; mt < 2; mt++) {
            int row0 = bm * HBM + wm * 32 + mt * 16 + g;
            int pos0 = (row0 & (SEQ - 1)) + sp0;
            int pos1 = ((row0 + 8) & (SEQ - 1)) + sp0;
            for (int nt = 0; nt < 8; nt++) {
                int col = bn * HBN + wn * 64 + nt * 8 + t2;
                float invf = invf_tbl[(col & 127) >> 1];
                float sn0;
                float cs0;
                sincosf(__fmul_rn((float)pos0, invf), &sn0, &cs0);
                float sn1;
                float cs1;
                sincosf(__fmul_rn((float)pos1, invf), &sn1, &cs1);
                float a0 = (c[mt][nt][0] * cs0 - c[mt][nt][1] * sn0) * rscale;
                float a1 = (c[mt][nt][0] * sn0 + c[mt][nt][1] * cs0) * rscale;
                float b0 = (c[mt][nt][2] * cs1 - c[mt][nt][3] * sn1) * rscale;
                float b1 = (c[mt][nt][2] * sn1 + c[mt][nt][3] * cs1) * rscale;
                *(__half2*)(Ch16 + (long)row0 * N + col)       = __floats2half2_rn(a0, a1);
                *(__half2*)(Ch16 + (long)(row0 + 8) * N + col) = __floats2half2_rn(b0, b1);
            }
        }
    }
}

// fused Q+K+V projections; rope folded into Q/K epilogues, V -> fp16
__global__ __launch_bounds__(256, 2)
void gemm_qkv(const __half* __restrict__ hx,
              const __half* __restrict__ hwq,
              const __half* __restrict__ hwk,
              const __half* __restrict__ hwv,
              __half* __restrict__ hq, __half* __restrict__ hk,
              __half* __restrict__ hv,
              const float* __restrict__ invf, const int* __restrict__ sp)
{
    extern __shared__ char hsm[];
    int idx = blockIdx.x;
    if (idx < 1024) {
        gemm_body(hx, hwq, nullptr, hq, DIM, DIM, idx >> 5, idx & 31, hsm,
                  2, invf, sp, 0.08838834764831845f);
    } else {
        int t = idx - 1024;
        if (t < 256) {
            gemm_body(hx, hwk, nullptr, hk, KV_DIM, DIM, t >> 3, t & 7, hsm,
                      2, invf, sp, 1.0f);
        } else {
            t -= 256;
            gemm_body(hx, hwv, nullptr, hv, KV_DIM, DIM, t >> 3, t & 7, hsm,
                      1, invf, sp, 1.0f);
        }
    }
}

__global__ __launch_bounds__(256, 2)
void gemm_wo(const __half* __restrict__ A, const __half* __restrict__ B,
             float* __restrict__ C, int N, int K)
{
    extern __shared__ char hsm[];
    gemm_body(A, B, C, nullptr, N, K, blockIdx.y, blockIdx.x, hsm,
              0, nullptr, nullptr, 1.0f);
}

// ==================================================================
// FP16 flash attention (proven, unchanged)
// ==================================================================
#define ASQ  0
#define ASK0 32768
#define ASK1 49152
#define ASV0 65536
#define ASV1 81920
#define ASPS 98304
#define ATTN_SMEM 114688

__global__ __launch_bounds__(256, 2)
void attn_f16_kernel(const __half* __restrict__ Q, const __half* __restrict__ Kg,
                     const __half* __restrict__ Vg, __half* __restrict__ O)
{
    extern __shared__ char smc[];
    const uint32_t su = (uint32_t)__cvta_generic_to_shared(smc);
    const int tid  = threadIdx.x;
    const int lane = tid & 31;
    const int warp = tid >> 5;
    const int qt = blockIdx.x;
    const int h  = blockIdx.y;
    const int b  = blockIdx.z;
    const int hk = h >> 2;
    const int q0 = qt * 128;

    const int grp  = lane >> 3;
    const int lr   = lane & 7;
    const int frow = lr + 8 * (grp & 1);
    const int gsel = grp >> 1;
    const int qrow = warp * 16 + frow;

    {
        int row = tid >> 1;
        int u0  = (tid & 1) * 8;
        const __half* src = Q + (long)(b * SEQ + q0 + row) * DIM + h * HD;
#pragma unroll
        for (int p = 0; p < 8; p++) {
            int u  = u0 + p;
            int uu = (u & 8) | ((u & 7) ^ (row & 7));
            cp_async16(su + ASQ + (uint32_t)(row * 256 + uu * 16), src + u * 8);
        }
        cp_commit();
    }

    const int lkrow = tid >> 2;
    const int lku   = tid & 3;
    auto load_kv = [&](int kt2, int bb2) {
        long roff = (long)(b * SEQ + kt2 * 64 + lkrow);
        const __half* ks = Kg + roff * KV_DIM + hk * HD;
        const __half* vs = Vg + roff * KV_DIM + hk * HD;
        uint32_t kd = su + (bb2 ? ASK1 : ASK0) + (uint32_t)(lkrow * 256);
        uint32_t vd = su + (bb2 ? ASV1 : ASV0) + (uint32_t)(lkrow * 256);
#pragma unroll
        for (int p = 0; p < 4; p++) {
            int u  = lku + p * 4;
            int uu = (u & 8) | ((u & 7) ^ (lkrow & 7));
            cp_async16(kd + (uint32_t)(uu * 16), ks + u * 8);
            cp_async16(vd + (uint32_t)(uu * 16), vs + u * 8);
        }
    };

    load_kv(0, 0);
    cp_commit();
    load_kv(1, 1);
    cp_commit();

    float oacc[16][4];
    for (int nt = 0; nt < 16; nt++) {
        for (int r = 0; r < 4; r++) {
            oacc[nt][r] = 0.f;
        }
    }
    float m0 = -1e30f, m1 = -1e30f, l0 = 0.f, l1 = 0.f;

    for (int kt = 0; kt < 32; kt++) {
        cp_wait<1>();
        __syncthreads();

        int bb = kt & 1;
        const uint32_t Kbase = su + (bb ? ASK1 : ASK0);
        const uint32_t Vbase = su + (bb ? ASV1 : ASV0);

        float sc[8][4];
        for (int nt = 0; nt < 8; nt++) {
            for (int r = 0; r < 4; r++) {
                sc[nt][r] = 0.f;
            }
        }
#pragma unroll
        for (int kk = 0; kk < 8; kk++) {
            int u = 2 * kk + gsel;
            uint32_t af[4];
            {
                int uu = (u & 8) | ((u & 7) ^ (qrow & 7));
                ldsm4(af[0], af[1], af[2], af[3],
                      su + ASQ + (uint32_t)(qrow * 256 + uu * 16));
            }
            uint32_t bf[4][4];
#pragma unroll
            for (int jp = 0; jp < 4; jp++) {
                int row = jp * 16 + frow;
                int uu  = (u & 8) | ((u & 7) ^ (row & 7));
                ldsm4(bf[jp][0], bf[jp][1], bf[jp][2], bf[jp][3],
                      Kbase + (uint32_t)(row * 256 + uu * 16));
            }
#pragma unroll
            for (int nt = 0; nt < 8; nt++) {
                mma_f16(sc[nt], af, bf[nt >> 1][nt & 1], bf[nt >> 1][(nt & 1) + 2]);
            }
        }

        {
            float mx0 = -1e30f, mx1 = -1e30f;
#pragma unroll
            for (int nt = 0; nt < 8; nt++) {
                mx0 = fmaxf(mx0, fmaxf(sc[nt][0], sc[nt][1]));
                mx1 = fmaxf(mx1, fmaxf(sc[nt][2], sc[nt][3]));
            }
            mx0 = fmaxf(mx0, __shfl_xor_sync(0xffffffffu, mx0, 1));
            mx0 = fmaxf(mx0, __shfl_xor_sync(0xffffffffu, mx0, 2));
            mx1 = fmaxf(mx1, __shfl_xor_sync(0xffffffffu, mx1, 1));
            mx1 = fmaxf(mx1, __shfl_xor_sync(0xffffffffu, mx1, 2));
            float nm0 = fmaxf(m0, mx0);
            float nm1 = fmaxf(m1, mx1);
            float cf0 = __expf(m0 - nm0);
            float cf1 = __expf(m1 - nm1);
            m0 = nm0;
            m1 = nm1;

            const int g  = lane >> 2;
            const int t2 = (lane & 3) * 2;
            const int prow0 = warp * 16 + g;
            const int prow1 = prow0 + 8;
            float ps0 = 0.f, ps1 = 0.f;
#pragma unroll
            for (int nt = 0; nt < 8; nt++) {
                float p0 = __expf(sc[nt][0] - nm0);
                float p1 = __expf(sc[nt][1] - nm0);
                float p2 = __expf(sc[nt][2] - nm1);
                float p3 = __expf(sc[nt][3] - nm1);
                ps0 += p0 + p1;
                ps1 += p2 + p3;
                __half2 h01 = __floats2half2_rn(p0, p1);
                __half2 h23 = __floats2half2_rn(p2, p3);
                int uu0 = nt ^ (prow0 & 7);
                int uu1 = nt ^ (prow1 & 7);
                *(__half2*)(smc + ASPS + prow0 * 128 + uu0 * 16 + t2 * 2) = h01;
                *(__half2*)(smc + ASPS + prow1 * 128 + uu1 * 16 + t2 * 2) = h23;
            }
            ps0 += __shfl_xor_sync(0xffffffffu, ps0, 1);
            ps0 += __shfl_xor_sync(0xffffffffu, ps0, 2);
            ps1 += __shfl_xor_sync(0xffffffffu, ps1, 1);
            ps1 += __shfl_xor_sync(0xffffffffu, ps1, 2);
            l0 = l0 * cf0 + ps0;
            l1 = l1 * cf1 + ps1;
#pragma unroll
            for (int nt = 0; nt < 16; nt++) {
                oacc[nt][0] *= cf0;
                oacc[nt][1] *= cf0;
                oacc[nt][2] *= cf1;
                oacc[nt][3] *= cf1;
            }
        }
        __syncwarp();

#pragma unroll
        for (int k2 = 0; k2 < 4; k2++) {
            uint32_t af[4];
            {
                int u  = 2 * k2 + gsel;
                int uu = u ^ (qrow & 7);
                ldsm4(af[0], af[1], af[2], af[3],
                      su + ASPS + (uint32_t)(qrow * 128 + uu * 16));
            }
            uint32_t vf[8][4];
#pragma unroll
            for (int jp = 0; jp < 8; jp++) {
                int row = k2 * 16 + frow;
                int u   = 2 * jp + gsel;
                int uu  = (u & 8) | ((u & 7) ^ (row & 7));
                ldsm4t(vf[jp][0], vf[jp][1], vf[jp][2], vf[jp][3],
                       Vbase + (uint32_t)(row * 256 + uu * 16));
            }
#pragma unroll
            for (int jp = 0; jp < 8; jp++) {
                mma_f16(oacc[jp * 2],     af, vf[jp][0], vf[jp][1]);
                mma_f16(oacc[jp * 2 + 1], af, vf[jp][2], vf[jp][3]);
            }
        }
        __syncthreads();

        if (kt + 2 < 32) {
            load_kv(kt + 2, bb);
        }
        cp_commit();
    }

    {
        float r0 = 1.f / l0;
        float r1 = 1.f / l1;
        const int g  = lane >> 2;
        const int t2 = (lane & 3) * 2;
        int row0 = q0 + warp * 16 + g;
        __half* op0 = O + (long)(b * SEQ + row0) * DIM + h * HD;
        __half* op1 = op0 + (long)8 * DIM;
#pragma unroll
        for (int nt = 0; nt < 16; nt++) {
            *(__half2*)(op0 + nt * 8 + t2) =
                __floats2half2_rn(oacc[nt][0] * r0, oacc[nt][1] * r0);
            *(__half2*)(op1 + nt * 8 + t2) =
                __floats2half2_rn(oacc[nt][2] * r1, oacc[nt][3] * r1);
        }
    }
}

// ==================================================================
// Launch
// ==================================================================
extern "C" void kernel_launch(void* const* d_in, const int* in_sizes, int n_in,
                              void* d_out, int out_size)
{
    (void)in_sizes;
    (void)n_in;
    (void)out_size;
    const float* x  = (const float*)d_in[0];
    const float* wq = (const float*)d_in[1];
    const float* wk = (const float*)d_in[2];
    const float* wv = (const float*)d_in[3];
    const float* wo = (const float*)d_in[4];
    const int*   sp = (const int*)d_in[5];
    float* out = (float*)d_out;

    __half* hx;
    __half* hwq;
    __half* hwk;
    __half* hwv;
    __half* hwo;
    __half* hq;
    __half* hkb;
    __half* hvb;
    __half* ho;
    float* invf;
    cudaGetSymbolAddress((void**)&hx,   g_hx);
    cudaGetSymbolAddress((void**)&hwq,  g_hwq);
    cudaGetSymbolAddress((void**)&hwk,  g_hwk);
    cudaGetSymbolAddress((void**)&hwv,  g_hwv);
    cudaGetSymbolAddress((void**)&hwo,  g_hwo);
    cudaGetSymbolAddress((void**)&hq,   g_hq);
    cudaGetSymbolAddress((void**)&hkb,  g_hk);
    cudaGetSymbolAddress((void**)&hvb,  g_hv);
    cudaGetSymbolAddress((void**)&ho,   g_ho);
    cudaGetSymbolAddress((void**)&invf, g_invf);

    cudaFuncSetAttribute(gemm_qkv,
                         cudaFuncAttributeMaxDynamicSharedMemorySize, HGEMM_SMEM);
    cudaFuncSetAttribute(gemm_wo,
                         cudaFuncAttributeMaxDynamicSharedMemorySize, HGEMM_SMEM);
    cudaFuncSetAttribute(attn_f16_kernel,
                         cudaFuncAttributeMaxDynamicSharedMemorySize, ATTN_SMEM);

    invf_kernel<<<1, 64>>>(invf);

    {
        int n4x  = MROWS * DIM / 4;
        int n4q  = DIM * DIM / 4;
        int n4kv = KV_DIM * DIM / 4;
        int total = n4x + n4q + 2 * n4kv + n4q;
        to_half5_kernel<<<(total + 255) / 256, 256>>>(
            x, hx, n4x, wq, hwq, n4q, wk, hwk, n4kv, wv, hwv, n4kv, wo, hwo, n4q);
    }

    gemm_qkv<<<1536, 256, HGEMM_SMEM>>>(hx, hwq, hwk, hwv, hq, hkb, hvb, invf, sp);

    dim3 ga(SEQ / 128, NHQ, BATCH);
    attn_f16_kernel<<<ga, 256, ATTN_SMEM>>>(hq, hkb, hvb, ho);

    dim3 gw(DIM / HBN, MROWS / HBM);
    gemm_wo<<<gw, 256, HGEMM_SMEM>>>(ho, hwo, out, DIM, DIM);
}